// round 1
// baseline (speedup 1.0000x reference)
#include <cuda_runtime.h>

#define H 128
#define W 128
#define NS 8
#define KH 5
#define KW 5
#define TY 32
#define SROWS (TY + 8)
#define SCOLS (W + 8)

__global__ __launch_bounds__(128)
void shifted_conv_kernel(const float* __restrict__ tens,
                         const float* __restrict__ filters,
                         const int* __restrict__ shifts,
                         float* __restrict__ out)
{
    __shared__ float s_in[SROWS][SCOLS];
    __shared__ float s_f[NS * KH * KW];
    __shared__ int   s_sh[NS * 2];

    const int n    = blockIdx.x;        // 0..255  (B*C)
    const int y0   = blockIdx.y * TY;   // 0,32,64,96
    const int tid  = threadIdx.x;
    const int lane = tid & 31;
    const int wrp  = tid >> 5;

    // Stage filters + shifts
    for (int i = tid; i < NS * KH * KW; i += 128) s_f[i] = filters[i];
    if (tid < NS * 2) s_sh[tid] = shifts[tid];

    // Stage input strip with 4-halo, zero-padded outside [0,128)^2
    const float* inp = tens + (size_t)n * (H * W);
    for (int idx = tid; idx < SROWS * SCOLS; idx += 128) {
        int r  = idx / SCOLS;
        int c  = idx - r * SCOLS;
        int gy = y0 - 4 + r;
        int gx = c - 4;
        float v = 0.0f;
        if (gy >= 0 && gy < H && gx >= 0 && gx < W)
            v = inp[gy * W + gx];
        s_in[r][c] = v;
    }
    __syncthreads();

    const int ybase = wrp * 8;  // each warp owns 8 output rows of the tile
    float* outn = out + (size_t)n * (NS * H * W) + (size_t)(y0 + ybase) * W;

    #pragma unroll 1
    for (int s = 0; s < NS; ++s) {
        const int sy = s_sh[2 * s + 0];
        const int sx = s_sh[2 * s + 1];

        // Filter taps into registers (reused across 4 b-subtiles * 8 rows)
        float f[KH][KW];
        #pragma unroll
        for (int i = 0; i < KH; ++i)
            #pragma unroll
            for (int j = 0; j < KW; ++j)
                f[i][j] = s_f[(s * KH + i) * KW + j];

        const int rowbase = ybase + 4 - sy;   // in [0, 28]

        #pragma unroll 1
        for (int b = 0; b < 4; ++b) {
            const int col = lane + 32 * b + 4 - sx;   // in [0, 131]

            float acc[8];
            #pragma unroll
            for (int y = 0; y < 8; ++y) acc[y] = 0.0f;

            // Stream 12 input rows; each row feeds up to 5 accumulators.
            #pragma unroll
            for (int k = 0; k < 12; ++k) {
                float cur[KW];
                #pragma unroll
                for (int j = 0; j < KW; ++j)
                    cur[j] = s_in[rowbase + k][col + j];
                #pragma unroll
                for (int y = 0; y < 8; ++y) {
                    const int i = k - y;            // compile-time per (k,y)
                    if (i >= 0 && i < KH) {
                        #pragma unroll
                        for (int j = 0; j < KW; ++j)
                            acc[y] += f[i][j] * cur[j];
                    }
                }
            }

            float* op = outn + (size_t)s * (H * W) + lane + 32 * b;
            #pragma unroll
            for (int y = 0; y < 8; ++y)
                op[y * W] = acc[y];
        }
    }
}

extern "C" void kernel_launch(void* const* d_in, const int* in_sizes, int n_in,
                              void* d_out, int out_size)
{
    const float* tens    = (const float*)d_in[0];
    const float* filters = (const float*)d_in[1];
    const int*   shifts  = (const int*)d_in[2];
    float*       out     = (float*)d_out;

    dim3 grid(256, H / TY);   // (B*C, y-tiles)
    shifted_conv_kernel<<<grid, 128>>>(tens, filters, shifts, out);
}

// round 2
// speedup vs baseline: 1.0339x; 1.0339x over previous
#include <cuda_runtime.h>
#include <cstdint>

#define H 128
#define W 128
#define NS 8
#define TY 32
#define SROWS (TY + 8)   // 40
#define SCOLS 140        // 128 + 8 halo + pad for aligned-pair over-read

__device__ __forceinline__ uint64_t fma2(uint64_t a, uint64_t b, uint64_t c) {
    uint64_t d;
    asm("fma.rn.f32x2 %0, %1, %2, %3;" : "=l"(d) : "l"(a), "l"(b), "l"(c));
    return d;
}
__device__ __forceinline__ uint64_t pack2(float lo, float hi) {
    uint64_t r;
    asm("mov.b64 %0, {%1, %2};" : "=l"(r) : "f"(lo), "f"(hi));
    return r;
}
__device__ __forceinline__ void unpack2(uint64_t v, float& lo, float& hi) {
    asm("mov.b64 {%0, %1}, %2;" : "=f"(lo), "=f"(hi) : "l"(v));
}

// Compute 8 rows x 2 cols of output for one (s, x-subtile).
// sbase points at s_in[rowbase][col_aligned]; PAR = parity of the true col
// (0: col == col_aligned; 1: col == col_aligned + 1). Warp-uniform.
template<int PAR>
__device__ __forceinline__ void conv_tile(const float* sbase, const uint64_t* fp,
                                          float* op)
{
    uint64_t acc[8];
    #pragma unroll
    for (int y = 0; y < 8; ++y) acc[y] = 0ull;   // (0.f, 0.f)

    #pragma unroll
    for (int k = 0; k < 12; ++k) {
        const float* r = sbase + k * SCOLS;
        uint64_t p0, p1, p2, p3, p4;
        if (PAR == 0) {
            // need v0..v5 at col..col+5 (col aligned)
            uint64_t q0 = *(const uint64_t*)(r + 0);  // (v0,v1)
            uint64_t q1 = *(const uint64_t*)(r + 2);  // (v2,v3)
            uint64_t q2 = *(const uint64_t*)(r + 4);  // (v4,v5)
            float a0, a1, b0, b1, c0, c1;
            unpack2(q0, a0, a1); unpack2(q1, b0, b1); unpack2(q2, c0, c1);
            p0 = q0;
            p1 = pack2(a1, b0);
            p2 = q1;
            p3 = pack2(b1, c0);
            p4 = q2;
        } else {
            // true col = aligned+1; need v'_1..v'_6 from v'_0..v'_7
            uint64_t q0 = *(const uint64_t*)(r + 0);  // (v'0,v'1)
            uint64_t q1 = *(const uint64_t*)(r + 2);  // (v'2,v'3)
            uint64_t q2 = *(const uint64_t*)(r + 4);  // (v'4,v'5)
            uint64_t q3 = *(const uint64_t*)(r + 6);  // (v'6,v'7)
            float a0, a1, b0, b1, c0, c1, d0, d1;
            unpack2(q0, a0, a1); unpack2(q1, b0, b1);
            unpack2(q2, c0, c1); unpack2(q3, d0, d1);
            p0 = pack2(a1, b0);
            p1 = q1;
            p2 = pack2(b1, c0);
            p3 = q2;
            p4 = pack2(c1, d0);
        }
        #pragma unroll
        for (int y = 0; y < 8; ++y) {
            const int i = k - y;               // compile-time after unroll
            if (i >= 0 && i < 5) {
                acc[y] = fma2(fp[i * 5 + 0], p0, acc[y]);
                acc[y] = fma2(fp[i * 5 + 1], p1, acc[y]);
                acc[y] = fma2(fp[i * 5 + 2], p2, acc[y]);
                acc[y] = fma2(fp[i * 5 + 3], p3, acc[y]);
                acc[y] = fma2(fp[i * 5 + 4], p4, acc[y]);
            }
        }
    }
    #pragma unroll
    for (int y = 0; y < 8; ++y)
        *(uint64_t*)(op + y * W) = acc[y];     // STG.64, 8B aligned (x even)
}

__global__ void __launch_bounds__(128, 5)
shifted_conv_kernel(const float* __restrict__ tens,
                    const float* __restrict__ filters,
                    const int* __restrict__ shifts,
                    float* __restrict__ out)
{
    __shared__ float s_in[SROWS][SCOLS];
    __shared__ float s_f[NS * 25];
    __shared__ int   s_sh[NS * 2];

    const int n    = blockIdx.x;        // 0..255 (B*C)
    const int y0   = blockIdx.y * TY;   // 0,32,64,96
    const int tid  = threadIdx.x;
    const int lane = tid & 31;
    const int wrp  = tid >> 5;

    for (int i = tid; i < NS * 25; i += 128) s_f[i] = filters[i];
    if (tid < NS * 2) s_sh[tid] = shifts[tid];

    const float* inp = tens + (size_t)n * (H * W);
    for (int idx = tid; idx < SROWS * SCOLS; idx += 128) {
        int r  = idx / SCOLS;
        int c  = idx - r * SCOLS;
        int gy = y0 - 4 + r;
        int gx = c - 4;
        float v = 0.0f;
        if (gy >= 0 && gy < H && gx >= 0 && gx < W)
            v = inp[gy * W + gx];
        s_in[r][c] = v;
    }
    __syncthreads();

    const int ybase = wrp * 8;          // 8 output rows per warp
    float* outw = out + (size_t)n * (NS * H * W) + (size_t)(y0 + ybase) * W;

    #pragma unroll 1
    for (int s = 0; s < NS; ++s) {
        const int sy = s_sh[2 * s + 0];
        const int sx = s_sh[2 * s + 1];

        // splat filter taps into packed pairs (reused for 2 subtiles * 16 outputs)
        uint64_t fp[25];
        #pragma unroll
        for (int t = 0; t < 25; ++t) {
            float f = s_f[s * 25 + t];
            fp[t] = pack2(f, f);
        }

        const int rowbase = ybase + 4 - sy;     // [0,28]
        const int col0    = 2 * lane + 4 - sx;  // parity == parity of sx
        float* ops = outw + (size_t)s * (H * W) + 2 * lane;

        if (!(sx & 1)) {
            const float* sb = &s_in[rowbase][col0];
            conv_tile<0>(sb,      fp, ops);
            conv_tile<0>(sb + 64, fp, ops + 64);
        } else {
            const float* sb = &s_in[rowbase][col0 - 1];
            conv_tile<1>(sb,      fp, ops);
            conv_tile<1>(sb + 64, fp, ops + 64);
        }
    }
}

extern "C" void kernel_launch(void* const* d_in, const int* in_sizes, int n_in,
                              void* d_out, int out_size)
{
    const float* tens    = (const float*)d_in[0];
    const float* filters = (const float*)d_in[1];
    const int*   shifts  = (const int*)d_in[2];
    float*       out     = (float*)d_out;

    dim3 grid(256, H / TY);   // (B*C, y-tiles)
    shifted_conv_kernel<<<grid, 128>>>(tens, filters, shifts, out);
}